// round 8
// baseline (speedup 1.0000x reference)
#include <cuda_runtime.h>

// Problem constants (from reference setup_inputs)
#define Bc    4
#define Nc    16384
#define Kc    27
#define BNc   (Bc * Nc)            // 65536
#define Tc    (BNc * Kc)           // 1769472
#define BASEc 70
#define BASE3 343000               // 70^3
#define TABLE_SIZE (Bc * BASE3)    // 1372000
#define SHIFTc 3

#define SCAN_BLOCK 256
#define SCAN_ITEMS 8
#define SCAN_TILE  (SCAN_BLOCK * SCAN_ITEMS)  // 2048
#define NTILES     (Tc / SCAN_TILE)           // 864 (exact)

// Scratch (__device__ globals per allocation-free rule).
// NOTE: device-global addresses must only be formed in DEVICE code — taking
// them in host code yields the host shadow symbol (round-7 bug: ATS made the
// bogus pointer silently writable).
__device__ __align__(16) int g_table[TABLE_SIZE];        // min t per key
__device__ int g_oi[TABLE_SIZE];                         // dense index per key
__device__ int g_keybase[BNc];                           // encoded center key per point
__device__ int g_bsum[NTILES];                           // per-tile unique counts
__device__ int g_bpre[NTILES];                           // exclusive prefix of tile counts
__device__ unsigned char g_flag[NTILES * SCAN_BLOCK];    // 8 flags per thread, per tile

// key delta per kernel offset k ('ij' meshgrid order)
__constant__ int c_delta[Kc] = {
    -4971, -4970, -4969,  -4901, -4900, -4899,  -4831, -4830, -4829,
      -71,   -70,   -69,     -1,     0,     1,     69,    70,    71,
     4829,  4830,  4831,   4899,  4900,  4901,   4969,  4970,  4971
};

__global__ void k_init() {
    int i = blockIdx.x * blockDim.x + threadIdx.x;
    if (i < TABLE_SIZE / 4)
        ((int4*)g_table)[i] = make_int4(0x7fffffff, 0x7fffffff, 0x7fffffff, 0x7fffffff);
}

// -1 fill of the out_key region (float4; 3*Tc divisible by 4, region 16B aligned)
__global__ void k_fill(float4* __restrict__ okey4) {
    int i = blockIdx.x * blockDim.x + threadIdx.x;
    if (i < 3 * Tc / 4) okey4[i] = make_float4(-1.f, -1.f, -1.f, -1.f);
}

// zero any harness padding past 6T+1 (launched only when present)
__global__ void k_tail(float* __restrict__ p, long long n) {
    long long i = (long long)blockIdx.x * blockDim.x + threadIdx.x;
    long long stride = (long long)gridDim.x * blockDim.x;
    for (; i < n; i += stride) p[i] = 0.0f;
}

// One thread per (point, offset): 1 atomic each, full occupancy.
__global__ void k_build(const int* __restrict__ coords,
                        const int* __restrict__ batch) {
    int t = blockIdx.x * blockDim.x + threadIdx.x;
    if (t >= Tc) return;
    int idx = t / Kc;
    int k   = t - idx * Kc;
    int x = coords[idx * 3 + 0];
    int y = coords[idx * 3 + 1];
    int z = coords[idx * 3 + 2];
    int b = batch[idx];
    int kb = b * BASE3 + ((x + SHIFTc) * BASEc + (y + SHIFTc)) * BASEc + (z + SHIFTc);
    if (k == 0) g_keybase[idx] = kb;
    atomicMin(&g_table[kb + c_delta[k]], t);
}

// Phase 1: per-tile flags (bitmask byte per thread) + tile aggregate.
__global__ void k_reduce() {
    __shared__ int warp_sums[SCAN_BLOCK / 32];
    int tile = blockIdx.x, tid = threadIdx.x;
    int base = tile * SCAN_TILE + tid * SCAN_ITEMS;

    unsigned m = 0;
    int s = 0;
#pragma unroll
    for (int j = 0; j < SCAN_ITEMS; j++) {
        int t   = base + j;
        int idx = t / Kc;
        int k   = t - idx * Kc;
        int key = g_keybase[idx] + c_delta[k];
        if (g_table[key] == t) { m |= (1u << j); s++; }
    }
    g_flag[tile * SCAN_BLOCK + tid] = (unsigned char)m;

    int lane = tid & 31, wid = tid >> 5;
#pragma unroll
    for (int d = 16; d; d >>= 1) s += __shfl_down_sync(0xffffffffu, s, d);
    if (lane == 0) warp_sums[wid] = s;
    __syncthreads();
    if (tid < 32) {
        int v = (tid < SCAN_BLOCK / 32) ? warp_sums[tid] : 0;
#pragma unroll
        for (int d = 16; d; d >>= 1) v += __shfl_down_sync(0xffffffffu, v, d);
        if (tid == 0) g_bsum[tile] = v;
    }
}

// Phase 2: one block scans the 864 tile totals; writes num_out.
__global__ void k_scantiles(float* __restrict__ out) {
    __shared__ int sh[1024];
    int i = threadIdx.x;
    int v = (i < NTILES) ? g_bsum[i] : 0;
    sh[i] = v;
    __syncthreads();
#pragma unroll
    for (int d = 1; d < 1024; d <<= 1) {
        int u = (i >= d) ? sh[i - d] : 0;
        __syncthreads();
        sh[i] += u;
        __syncthreads();
    }
    if (i < NTILES) g_bpre[i] = sh[i] - v;
    if (i == NTILES - 1) out[6LL * Tc] = (float)sh[i];   // num_out
}

// Phase 3: block scan of saved flag popcounts; first occurrences get dense
// index oi -> write g_oi[key] and out_key[oi].
__global__ void k_scatter(float* __restrict__ out) {
    __shared__ int warp_sums[SCAN_BLOCK / 32];
    int tile = blockIdx.x, tid = threadIdx.x;
    unsigned m = g_flag[tile * SCAN_BLOCK + tid];
    int s = __popc(m);

    int lane = tid & 31, wid = tid >> 5;
    int incl = s;
#pragma unroll
    for (int d = 1; d < 32; d <<= 1) {
        int v = __shfl_up_sync(0xffffffffu, incl, d);
        if (lane >= d) incl += v;
    }
    if (lane == 31) warp_sums[wid] = incl;
    __syncthreads();
    if (wid == 0) {
        int v = (lane < SCAN_BLOCK / 32) ? warp_sums[lane] : 0;
#pragma unroll
        for (int d = 1; d < 32; d <<= 1) {
            int u = __shfl_up_sync(0xffffffffu, v, d);
            if (lane >= d) v += u;
        }
        if (lane < SCAN_BLOCK / 32) warp_sums[lane] = v;
    }
    __syncthreads();

    if (!m) return;
    int run = g_bpre[tile] + ((wid == 0) ? 0 : warp_sums[wid - 1]) + incl - s;
    int base = tile * SCAN_TILE + tid * SCAN_ITEMS;
#pragma unroll
    for (int j = 0; j < SCAN_ITEMS; j++) {
        if ((m >> j) & 1u) {
            int t   = base + j;
            int idx = t / Kc;
            int k   = t - idx * Kc;
            int key = g_keybase[idx] + c_delta[k];
            g_oi[key] = run;
            int rem = key % BASE3;
            int xx = rem / (BASEc * BASEc) - SHIFTc;
            int yy = (rem / BASEc) % BASEc - SHIFTc;
            int zz = rem % BASEc - SHIFTc;
            float* p = out + 3LL * Tc + 3LL * run;
            p[0] = (float)xx; p[1] = (float)yy; p[2] = (float)zz;
            run++;
        }
    }
}

// Final pass: in_idx, out_idx, rel_pos — three float4 streams.
__global__ void k_outidx(float* __restrict__ out) {
    int i = blockIdx.x * blockDim.x + threadIdx.x;
    if (i >= Tc / 4) return;
    int t0 = i * 4;
    float4 a, b, c;
#pragma unroll
    for (int j = 0; j < 4; j++) {
        int t   = t0 + j;
        int idx = t / Kc;
        int k   = t - idx * Kc;
        int key = g_keybase[idx] + c_delta[k];
        (&a.x)[j] = (float)(idx & (Nc - 1));
        (&b.x)[j] = (float)g_oi[key];
        (&c.x)[j] = (float)k;
    }
    ((float4*)out)[i]              = a;   // in_idx
    ((float4*)(out + 1LL * Tc))[i] = b;   // out_idx
    ((float4*)(out + 2LL * Tc))[i] = c;   // rel_pos
}

extern "C" void kernel_launch(void* const* d_in, const int* in_sizes, int n_in,
                              void* d_out, int out_size) {
    // Identify inputs by SIZE: coordinates = [B,N,3] (3*BNc), batch = [B,N] (BNc).
    const int* coords = (const int*)d_in[0];
    const int* batch  = (const int*)d_in[n_in > 1 ? 1 : 0];
    for (int i = 0; i < n_in; i++) {
        if (in_sizes[i] == 3 * BNc) coords = (const int*)d_in[i];
        else if (in_sizes[i] == BNc) batch = (const int*)d_in[i];
    }
    float* out = (float*)d_out;
    long long osz = (long long)out_size;

    long long tail = osz - (6LL * Tc + 1);
    if (tail > 0) k_tail<<<512, 256>>>(out + 6LL * Tc + 1, tail);

    k_init<<<(TABLE_SIZE / 4 + 255) / 256, 256>>>();
    k_fill<<<(3 * Tc / 4 + 255) / 256, 256>>>((float4*)(out + 3LL * Tc));
    k_build<<<(Tc + 255) / 256, 256>>>(coords, batch);
    k_reduce<<<NTILES, SCAN_BLOCK>>>();
    k_scantiles<<<1, 1024>>>(out);
    k_scatter<<<NTILES, SCAN_BLOCK>>>(out);
    k_outidx<<<(Tc / 4 + 255) / 256, 256>>>(out);
}

// round 9
// speedup vs baseline: 1.1039x; 1.1039x over previous
#include <cuda_runtime.h>

// Problem constants (from reference setup_inputs)
#define Bc    4
#define Nc    16384
#define Kc    27
#define BNc   (Bc * Nc)            // 65536
#define Tc    (BNc * Kc)           // 1769472
#define BASEc 70
#define BASE3 343000               // 70^3
#define TABLE_SIZE (Bc * BASE3)    // 1372000
#define SHIFTc 3

#define NWORDS (Tc / 32)           // 55296 bitmask words (exact)
#define S1_BLOCKS (NWORDS / 256)   // 216 (exact)

// Scratch (__device__ globals). Addresses formed ONLY in device code
// (round-7 lesson: host-side &g_sym is the shadow symbol; ATS hides the bug).
__device__ __align__(16) int g_table[TABLE_SIZE];     // min t per key (INT_MAX empty)
__device__ int g_oi[TABLE_SIZE];                      // dense rank per key
__device__ int g_keybase[BNc];                        // encoded center key per point
__device__ __align__(16) unsigned g_bits[NWORDS];     // bit t set <=> t is a first occurrence
__device__ int g_wordpre[NWORDS];                     // intra-tile exclusive popc prefix per word
__device__ int g_bsum2[S1_BLOCKS];                    // per-tile popc totals
__device__ int g_bpre2[S1_BLOCKS];                    // exclusive prefix of tile totals

// key delta per kernel offset k ('ij' meshgrid order)
__constant__ int c_delta[Kc] = {
    -4971, -4970, -4969,  -4901, -4900, -4899,  -4831, -4830, -4829,
      -71,   -70,   -69,     -1,     0,     1,     69,    70,    71,
     4829,  4830,  4831,   4899,  4900,  4901,   4969,  4970,  4971
};

// Fused fills: table <- INT_MAX, bitmask <- 0, out_key region <- -1. All int4.
#define PREP_A (TABLE_SIZE / 4)            // 343000
#define PREP_B (NWORDS / 4)                // 13824
#define PREP_C (3 * Tc / 4)                // 1327104
#define PREP_TOTAL (PREP_A + PREP_B + PREP_C)
__global__ void k_prep(float4* __restrict__ okey4) {
    int i = blockIdx.x * blockDim.x + threadIdx.x;
    if (i < PREP_A) {
        ((int4*)g_table)[i] = make_int4(0x7fffffff, 0x7fffffff, 0x7fffffff, 0x7fffffff);
    } else if (i < PREP_A + PREP_B) {
        ((int4*)g_bits)[i - PREP_A] = make_int4(0, 0, 0, 0);
    } else if (i < PREP_TOTAL) {
        okey4[i - PREP_A - PREP_B] = make_float4(-1.f, -1.f, -1.f, -1.f);
    }
}

// zero any harness padding past 6T+1 (launched only when present)
__global__ void k_tail(float* __restrict__ p, long long n) {
    long long i = (long long)blockIdx.x * blockDim.x + threadIdx.x;
    long long stride = (long long)gridDim.x * blockDim.x;
    for (; i < n; i += stride) p[i] = 0.0f;
}

// One thread per (point, offset): 1 spread atomic each.
__global__ void k_build(const int* __restrict__ coords,
                        const int* __restrict__ batch) {
    int t = blockIdx.x * blockDim.x + threadIdx.x;
    if (t >= Tc) return;
    int idx = t / Kc;
    int k   = t - idx * Kc;
    int x = coords[idx * 3 + 0];
    int y = coords[idx * 3 + 1];
    int z = coords[idx * 3 + 2];
    int b = batch[idx];
    int kb = b * BASE3 + ((x + SHIFTc) * BASEc + (y + SHIFTc)) * BASEc + (z + SHIFTc);
    if (k == 0) g_keybase[idx] = kb;
    atomicMin(&g_table[kb + c_delta[k]], t);
}

// Table pass: occupied key -> set bit at its min-t.
__global__ void k_bitset() {
    int i = blockIdx.x * blockDim.x + threadIdx.x;
    if (i >= TABLE_SIZE / 4) return;
    int4 v = ((const int4*)g_table)[i];
#pragma unroll
    for (int j = 0; j < 4; j++) {
        int ft = (&v.x)[j];
        if (ft != 0x7fffffff)
            atomicOr(&g_bits[ft >> 5], 1u << (ft & 31));
    }
}

// Level-1 scan: 216 blocks x 256 words; per-word exclusive popc prefix + tile totals.
__global__ void k_scan1() {
    __shared__ int warp_sums[8];
    int tid = threadIdx.x;
    int w = blockIdx.x * 256 + tid;
    int c = __popc(g_bits[w]);

    int lane = tid & 31, wid = tid >> 5;
    int incl = c;
#pragma unroll
    for (int d = 1; d < 32; d <<= 1) {
        int v = __shfl_up_sync(0xffffffffu, incl, d);
        if (lane >= d) incl += v;
    }
    if (lane == 31) warp_sums[wid] = incl;
    __syncthreads();
    if (wid == 0) {
        int v = (lane < 8) ? warp_sums[lane] : 0;
#pragma unroll
        for (int d = 1; d < 8; d <<= 1) {
            int u = __shfl_up_sync(0xffffffffu, v, d);
            if (lane >= d) v += u;
        }
        if (lane < 8) warp_sums[lane] = v;
    }
    __syncthreads();
    g_wordpre[w] = ((wid == 0) ? 0 : warp_sums[wid - 1]) + incl - c;  // exclusive
    if (tid == 255) g_bsum2[blockIdx.x] = warp_sums[7];
}

// Level-2 scan: one block over the 216 tile totals; writes num_out.
__global__ void k_scan2(float* __restrict__ out) {
    __shared__ int sh[256];
    int i = threadIdx.x;
    int v = (i < S1_BLOCKS) ? g_bsum2[i] : 0;
    sh[i] = v;
    __syncthreads();
#pragma unroll
    for (int d = 1; d < 256; d <<= 1) {
        int u = (i >= d) ? sh[i - d] : 0;
        __syncthreads();
        sh[i] += u;
        __syncthreads();
    }
    if (i < S1_BLOCKS) g_bpre2[i] = sh[i] - v;
    if (i == S1_BLOCKS - 1) out[6LL * Tc] = (float)sh[i];   // num_out
}

// Table pass: occupied key -> rank via bitmask prefix; write g_oi + out_key.
__global__ void k_assign(float* __restrict__ out) {
    int i = blockIdx.x * blockDim.x + threadIdx.x;
    if (i >= TABLE_SIZE / 4) return;
    int4 v = ((const int4*)g_table)[i];
#pragma unroll
    for (int j = 0; j < 4; j++) {
        int ft = (&v.x)[j];
        if (ft == 0x7fffffff) continue;
        int key = i * 4 + j;
        int w = ft >> 5;
        unsigned mask = (1u << (ft & 31)) - 1u;
        int rank = g_bpre2[w >> 8] + g_wordpre[w] + __popc(g_bits[w] & mask);
        g_oi[key] = rank;
        int rem = key % BASE3;
        int xx = rem / (BASEc * BASEc) - SHIFTc;
        int yy = (rem / BASEc) % BASEc - SHIFTc;
        int zz = rem % BASEc - SHIFTc;
        float* p = out + 3LL * Tc + 3LL * rank;
        p[0] = (float)xx; p[1] = (float)yy; p[2] = (float)zz;
    }
}

// Final pass: in_idx, out_idx, rel_pos — three float4 streams. (Proven in r8.)
__global__ void k_outidx(float* __restrict__ out) {
    int i = blockIdx.x * blockDim.x + threadIdx.x;
    if (i >= Tc / 4) return;
    int t0 = i * 4;
    float4 a, b, c;
#pragma unroll
    for (int j = 0; j < 4; j++) {
        int t   = t0 + j;
        int idx = t / Kc;
        int k   = t - idx * Kc;
        int key = g_keybase[idx] + c_delta[k];
        (&a.x)[j] = (float)(idx & (Nc - 1));
        (&b.x)[j] = (float)g_oi[key];
        (&c.x)[j] = (float)k;
    }
    ((float4*)out)[i]              = a;   // in_idx
    ((float4*)(out + 1LL * Tc))[i] = b;   // out_idx
    ((float4*)(out + 2LL * Tc))[i] = c;   // rel_pos
}

extern "C" void kernel_launch(void* const* d_in, const int* in_sizes, int n_in,
                              void* d_out, int out_size) {
    // Identify inputs by SIZE: coordinates = [B,N,3] (3*BNc), batch = [B,N] (BNc).
    const int* coords = (const int*)d_in[0];
    const int* batch  = (const int*)d_in[n_in > 1 ? 1 : 0];
    for (int i = 0; i < n_in; i++) {
        if (in_sizes[i] == 3 * BNc) coords = (const int*)d_in[i];
        else if (in_sizes[i] == BNc) batch = (const int*)d_in[i];
    }
    float* out = (float*)d_out;
    long long osz = (long long)out_size;

    long long tail = osz - (6LL * Tc + 1);
    if (tail > 0) k_tail<<<512, 256>>>(out + 6LL * Tc + 1, tail);

    k_prep<<<(PREP_TOTAL + 255) / 256, 256>>>((float4*)(out + 3LL * Tc));
    k_build<<<(Tc + 255) / 256, 256>>>(coords, batch);
    k_bitset<<<(TABLE_SIZE / 4 + 255) / 256, 256>>>();
    k_scan1<<<S1_BLOCKS, 256>>>();
    k_scan2<<<1, 256>>>(out);
    k_assign<<<(TABLE_SIZE / 4 + 255) / 256, 256>>>(out);
    k_outidx<<<(Tc / 4 + 255) / 256, 256>>>(out);
}